// round 14
// baseline (speedup 1.0000x reference)
#include <cuda_runtime.h>
#include <cstddef>
#include <cstdint>

// Adaptive-LIF forward. B=16384 independent rows, L=2048 serial steps.
// out[0:B*L] = spikes, out[B*L:2BL] = cumulative spike counts. Row-major.
//
// Design: 512 single-warp CTAs, 32 rows/warp. Per 32-step chunk:
//   cp.async stages the chunk (coalesced) into a per-warp row-major tile
//   (stride 36 floats -> conflict-free .128 shared access, no transpose),
//   each thread pulls its row into registers, runs the recurrence in pure
//   register math, writes results through shared for coalesced STG.128.
// Only __syncwarp() — no CTA barriers anywhere.

#define LLEN   2048
#define CCH    32            // time-chunk
#define NCH    (LLEN / CCH)  // 64
#define STRIDE 36            // floats per tile row (pad: 36 mod 32 = 4 -> conflict-free .128)

__global__ void __launch_bounds__(32)
lif_kernel(const float* __restrict__ I,
           float* __restrict__ outSpk,
           float* __restrict__ outNum)
{
    __shared__ float IN0[32 * STRIDE];
    __shared__ float IN1[32 * STRIDE];
    __shared__ float SP [32 * STRIDE];
    __shared__ float SN [32 * STRIDE];

    const int lane = threadIdx.x;
    const size_t rowBase = (size_t)blockIdx.x * 32;
    const float* __restrict__ Ib = I      + rowBase * LLEN;
    float* __restrict__ Sb       = outSpk + rowBase * LLEN;
    float* __restrict__ Nb       = outNum + rowBase * LLEN;

    // Coalesced lane mapping: 8 lanes cover one row's 128B chunk segment.
    const int j   = lane & 7;   // float4 column within the 32-float chunk
    const int lr0 = lane >> 3;  // row group offset

    // ---- prefetch chunk 0 into IN0 via cp.async ----
    {
        #pragma unroll
        for (int m = 0; m < 8; m++) {
            const int lr = m * 4 + lr0;
            const float* g = Ib + (size_t)lr * LLEN + j * 4;
            const uint32_t s =
                (uint32_t)__cvta_generic_to_shared(&IN0[lr * STRIDE + j * 4]);
            asm volatile("cp.async.cg.shared.global [%0], [%1], 16;\n"
                         :: "r"(s), "l"(g));
        }
        asm volatile("cp.async.commit_group;\n");
    }

    float v = 0.0f, a = 0.0f, snum = 0.0f;
    float in[CCH], sn[CCH];
    float4* in4 = reinterpret_cast<float4*>(in);
    float4* sn4 = reinterpret_cast<float4*>(sn);

    for (int k = 0; k < NCH; k++) {
        float* __restrict__ INc = (k & 1) ? IN1 : IN0;
        float* __restrict__ INn = (k & 1) ? IN0 : IN1;

        // current chunk ready
        asm volatile("cp.async.wait_group 0;\n" ::: "memory");
        __syncwarp();

        // ---- row -> registers (conflict-free LDS.128, out of the chain) ----
        #pragma unroll
        for (int m = 0; m < 8; m++)
            in4[m] = *reinterpret_cast<const float4*>(&INc[lane * STRIDE + m * 4]);

        // ---- issue prefetch of chunk k+1 (hidden under compute+writeout) ----
        if (k + 1 < NCH) {
            const float* __restrict__ src = Ib + (size_t)(k + 1) * CCH;
            #pragma unroll
            for (int m = 0; m < 8; m++) {
                const int lr = m * 4 + lr0;
                const float* g = src + (size_t)lr * LLEN + j * 4;
                const uint32_t s =
                    (uint32_t)__cvta_generic_to_shared(&INn[lr * STRIDE + j * 4]);
                asm volatile("cp.async.cg.shared.global [%0], [%1], 16;\n"
                             :: "r"(s), "l"(g));
            }
            asm volatile("cp.async.commit_group;\n");
        }

        // ---- serial LIF, pure register math (exact R2 expressions) ----
        #pragma unroll
        for (int t = 0; t < CCH; t++) {
            const float Iv = in[t];
            const float th = 1.0f + 1.5f * a;   // OLD a (ref order)
            v = v - v * 0.05f + Iv;             // v += I - v/tau
            const bool fired = (v >= th);
            const float s = fired ? 1.0f : 0.0f;
            snum += s;
            in[t] = s;                          // spike overwrites input reg
            sn[t] = snum;
            v = fired ? -0.5f : v;              // detached reset
            a = a - a * 0.01f + s;              // a += s - a/tau_adapt
        }

        // ---- results -> shared (conflict-free STS.128) ----
        #pragma unroll
        for (int m = 0; m < 8; m++) {
            *reinterpret_cast<float4*>(&SP[lane * STRIDE + m * 4]) = in4[m];
            *reinterpret_cast<float4*>(&SN[lane * STRIDE + m * 4]) = sn4[m];
        }
        __syncwarp();

        // ---- coalesced gather + STG.128 ----
        float* __restrict__ so = Sb + (size_t)k * CCH;
        float* __restrict__ no = Nb + (size_t)k * CCH;
        #pragma unroll
        for (int m = 0; m < 8; m++) {
            const int lr = m * 4 + lr0;
            const float4 sv = *reinterpret_cast<const float4*>(&SP[lr * STRIDE + j * 4]);
            const float4 nv = *reinterpret_cast<const float4*>(&SN[lr * STRIDE + j * 4]);
            *reinterpret_cast<float4*>(so + (size_t)lr * LLEN + j * 4) = sv;
            *reinterpret_cast<float4*>(no + (size_t)lr * LLEN + j * 4) = nv;
        }
        // next iteration's top __syncwarp orders these LDS against the next STS
    }
}

extern "C" void kernel_launch(void* const* d_in, const int* in_sizes, int n_in,
                              void* d_out, int out_size)
{
    const float* I = (const float*)d_in[0];
    const size_t total = (size_t)in_sizes[0];   // B * L
    const int B = (int)(total / LLEN);          // 16384

    float* outSpk = (float*)d_out;
    float* outNum = outSpk + total;

    lif_kernel<<<B / 32, 32>>>(I, outSpk, outNum);  // 512 single-warp CTAs
}

// round 15
// speedup vs baseline: 1.0003x; 1.0003x over previous
#include <cuda_runtime.h>
#include <cstddef>
#include <cstdint>

// Adaptive-LIF forward. B=16384 independent rows, L=2048 serial steps.
// out[0:B*L] = spikes, out[B*L:2BL] = cumulative spike counts. Row-major.
//
// Design: 512 single-warp CTAs, 32 rows/warp. Per 32-step chunk:
//   cp.async stages the chunk (coalesced) into a per-warp row-major tile
//   (stride 36 floats -> conflict-free .128 shared access, no transpose),
//   each thread pulls its row into registers, runs the recurrence in pure
//   register math, writes results through shared for coalesced STG.128.
// Only __syncwarp() — no CTA barriers anywhere.

#define LLEN   2048
#define CCH    32            // time-chunk
#define NCH    (LLEN / CCH)  // 64
#define STRIDE 36            // floats per tile row (pad: 36 mod 32 = 4 -> conflict-free .128)

__global__ void __launch_bounds__(32)
lif_kernel(const float* __restrict__ I,
           float* __restrict__ outSpk,
           float* __restrict__ outNum)
{
    __shared__ float IN0[32 * STRIDE];
    __shared__ float IN1[32 * STRIDE];
    __shared__ float SP [32 * STRIDE];
    __shared__ float SN [32 * STRIDE];

    const int lane = threadIdx.x;
    const size_t rowBase = (size_t)blockIdx.x * 32;
    const float* __restrict__ Ib = I      + rowBase * LLEN;
    float* __restrict__ Sb       = outSpk + rowBase * LLEN;
    float* __restrict__ Nb       = outNum + rowBase * LLEN;

    // Coalesced lane mapping: 8 lanes cover one row's 128B chunk segment.
    const int j   = lane & 7;   // float4 column within the 32-float chunk
    const int lr0 = lane >> 3;  // row group offset

    // ---- prefetch chunk 0 into IN0 via cp.async ----
    {
        #pragma unroll
        for (int m = 0; m < 8; m++) {
            const int lr = m * 4 + lr0;
            const float* g = Ib + (size_t)lr * LLEN + j * 4;
            const uint32_t s =
                (uint32_t)__cvta_generic_to_shared(&IN0[lr * STRIDE + j * 4]);
            asm volatile("cp.async.cg.shared.global [%0], [%1], 16;\n"
                         :: "r"(s), "l"(g));
        }
        asm volatile("cp.async.commit_group;\n");
    }

    float v = 0.0f, a = 0.0f, snum = 0.0f;
    float in[CCH], sn[CCH];
    float4* in4 = reinterpret_cast<float4*>(in);
    float4* sn4 = reinterpret_cast<float4*>(sn);

    for (int k = 0; k < NCH; k++) {
        float* __restrict__ INc = (k & 1) ? IN1 : IN0;
        float* __restrict__ INn = (k & 1) ? IN0 : IN1;

        // current chunk ready
        asm volatile("cp.async.wait_group 0;\n" ::: "memory");
        __syncwarp();

        // ---- row -> registers (conflict-free LDS.128, out of the chain) ----
        #pragma unroll
        for (int m = 0; m < 8; m++)
            in4[m] = *reinterpret_cast<const float4*>(&INc[lane * STRIDE + m * 4]);

        // ---- issue prefetch of chunk k+1 (hidden under compute+writeout) ----
        if (k + 1 < NCH) {
            const float* __restrict__ src = Ib + (size_t)(k + 1) * CCH;
            #pragma unroll
            for (int m = 0; m < 8; m++) {
                const int lr = m * 4 + lr0;
                const float* g = src + (size_t)lr * LLEN + j * 4;
                const uint32_t s =
                    (uint32_t)__cvta_generic_to_shared(&INn[lr * STRIDE + j * 4]);
                asm volatile("cp.async.cg.shared.global [%0], [%1], 16;\n"
                             :: "r"(s), "l"(g));
            }
            asm volatile("cp.async.commit_group;\n");
        }

        // ---- serial LIF, pure register math (exact R2 expressions) ----
        #pragma unroll
        for (int t = 0; t < CCH; t++) {
            const float Iv = in[t];
            const float th = 1.0f + 1.5f * a;   // OLD a (ref order)
            v = v - v * 0.05f + Iv;             // v += I - v/tau
            const bool fired = (v >= th);
            const float s = fired ? 1.0f : 0.0f;
            snum += s;
            in[t] = s;                          // spike overwrites input reg
            sn[t] = snum;
            v = fired ? -0.5f : v;              // detached reset
            a = a - a * 0.01f + s;              // a += s - a/tau_adapt
        }

        // ---- results -> shared (conflict-free STS.128) ----
        #pragma unroll
        for (int m = 0; m < 8; m++) {
            *reinterpret_cast<float4*>(&SP[lane * STRIDE + m * 4]) = in4[m];
            *reinterpret_cast<float4*>(&SN[lane * STRIDE + m * 4]) = sn4[m];
        }
        __syncwarp();

        // ---- coalesced gather + STG.128 ----
        float* __restrict__ so = Sb + (size_t)k * CCH;
        float* __restrict__ no = Nb + (size_t)k * CCH;
        #pragma unroll
        for (int m = 0; m < 8; m++) {
            const int lr = m * 4 + lr0;
            const float4 sv = *reinterpret_cast<const float4*>(&SP[lr * STRIDE + j * 4]);
            const float4 nv = *reinterpret_cast<const float4*>(&SN[lr * STRIDE + j * 4]);
            *reinterpret_cast<float4*>(so + (size_t)lr * LLEN + j * 4) = sv;
            *reinterpret_cast<float4*>(no + (size_t)lr * LLEN + j * 4) = nv;
        }
        // next iteration's top __syncwarp orders these LDS against the next STS
    }
}

extern "C" void kernel_launch(void* const* d_in, const int* in_sizes, int n_in,
                              void* d_out, int out_size)
{
    const float* I = (const float*)d_in[0];
    const size_t total = (size_t)in_sizes[0];   // B * L
    const int B = (int)(total / LLEN);          // 16384

    float* outSpk = (float*)d_out;
    float* outNum = outSpk + total;

    lif_kernel<<<B / 32, 32>>>(I, outSpk, outNum);  // 512 single-warp CTAs
}

// round 17
// speedup vs baseline: 1.4760x; 1.4756x over previous
#include <cuda_runtime.h>
#include <cstddef>
#include <cstdint>

// Adaptive-LIF forward. B=16384 independent rows, L=2048 serial steps.
// out[0:B*L] = spikes, out[B*L:2BL] = cumulative spike counts. Row-major.
//
// 512 single-warp CTAs, 32 rows/warp, 32-step chunks.
// 4-deep cp.async input pipeline: exactly ONE commit_group per iteration
// (empty in the tail), so wait_group DEPTH-2 at the chunk top completes
// exactly chunk k's group, issued 3 chunks earlier. Recurrence in pure
// register math with exact reference op order (rel_err == 0.0 previously).
// Stride-36 smem tiles -> conflict-free .128; staged coalesced STG.128.

#define LLEN   2048
#define CCH    32            // time-chunk
#define NCH    (LLEN / CCH)  // 64
#define STRIDE 36            // pad: 36 mod 32 = 4 -> conflict-free .128 access
#define DEPTH  4             // input pipeline depth

#define CP_ASYNC16(smem_u32, gptr)                                   \
    asm volatile("cp.async.cg.shared.global [%0], [%1], 16;\n"       \
                 :: "r"(smem_u32), "l"(gptr))
#define CP_COMMIT() asm volatile("cp.async.commit_group;\n")

__global__ void __launch_bounds__(32)
lif_kernel(const float* __restrict__ I,
           float* __restrict__ outSpk,
           float* __restrict__ outNum)
{
    __shared__ float IN[DEPTH][32 * STRIDE];
    __shared__ float SP[32 * STRIDE];
    __shared__ float SN[32 * STRIDE];

    const int lane = threadIdx.x;
    const size_t rowBase = (size_t)blockIdx.x * 32;
    const float* __restrict__ Ib = I      + rowBase * LLEN;
    float* __restrict__ Sb       = outSpk + rowBase * LLEN;
    float* __restrict__ Nb       = outNum + rowBase * LLEN;

    // Coalesced lane mapping: 8 lanes cover one row's 128B chunk segment.
    const int j   = lane & 7;   // float4 column within the 32-float chunk
    const int lr0 = lane >> 3;  // row group offset

    // ---- prologue: issue chunks 0..DEPTH-2 as separate commit groups ----
    #pragma unroll
    for (int p = 0; p < DEPTH - 1; p++) {
        const float* __restrict__ src = Ib + (size_t)p * CCH;
        #pragma unroll
        for (int m = 0; m < 8; m++) {
            const int lr = m * 4 + lr0;
            const float* g = src + (size_t)lr * LLEN + j * 4;
            const uint32_t s =
                (uint32_t)__cvta_generic_to_shared(&IN[p][lr * STRIDE + j * 4]);
            CP_ASYNC16(s, g);
        }
        CP_COMMIT();
    }

    float v = 0.0f, a = 0.0f, snum = 0.0f;
    float in[CCH], sn[CCH];
    float4* in4 = reinterpret_cast<float4*>(in);
    float4* sn4 = reinterpret_cast<float4*>(sn);

    for (int k = 0; k < NCH; k++) {
        float* __restrict__ INc = IN[k & (DEPTH - 1)];

        // Exactly one group is committed per iteration (empty in the tail),
        // so "<= DEPTH-2 pending" completes precisely chunk k's group.
        asm volatile("cp.async.wait_group %0;\n" :: "n"(DEPTH - 2) : "memory");
        __syncwarp();

        // ---- row -> registers (conflict-free LDS.128, out of the chain) ----
        #pragma unroll
        for (int m = 0; m < 8; m++)
            in4[m] = *reinterpret_cast<const float4*>(&INc[lane * STRIDE + m * 4]);

        // ---- issue prefetch of chunk k+DEPTH-1 (3 chunks ahead) ----
        if (k + DEPTH - 1 < NCH) {
            float* __restrict__ INn = IN[(k + DEPTH - 1) & (DEPTH - 1)];
            const float* __restrict__ src = Ib + (size_t)(k + DEPTH - 1) * CCH;
            #pragma unroll
            for (int m = 0; m < 8; m++) {
                const int lr = m * 4 + lr0;
                const float* g = src + (size_t)lr * LLEN + j * 4;
                const uint32_t s =
                    (uint32_t)__cvta_generic_to_shared(&INn[lr * STRIDE + j * 4]);
                CP_ASYNC16(s, g);
            }
        }
        CP_COMMIT();   // UNCONDITIONAL: empty group in the tail keeps the
                       // pending-count invariant so wait_group never no-ops.

        // ---- serial LIF, pure register math (exact reference op order) ----
        #pragma unroll
        for (int t = 0; t < CCH; t++) {
            const float Iv = in[t];
            const float th = 1.0f + 1.5f * a;   // OLD a (ref order)
            v = v - v * 0.05f + Iv;             // v += I - v/tau
            const bool fired = (v >= th);
            const float s = fired ? 1.0f : 0.0f;
            snum += s;
            in[t] = s;                          // spike overwrites input reg
            sn[t] = snum;
            v = fired ? -0.5f : v;              // detached reset
            a = a - a * 0.01f + s;              // a += s - a/tau_adapt
        }

        // ---- results -> shared (conflict-free STS.128) ----
        #pragma unroll
        for (int m = 0; m < 8; m++) {
            *reinterpret_cast<float4*>(&SP[lane * STRIDE + m * 4]) = in4[m];
            *reinterpret_cast<float4*>(&SN[lane * STRIDE + m * 4]) = sn4[m];
        }
        __syncwarp();

        // ---- coalesced gather + STG.128 ----
        float* __restrict__ so = Sb + (size_t)k * CCH;
        float* __restrict__ no = Nb + (size_t)k * CCH;
        #pragma unroll
        for (int m = 0; m < 8; m++) {
            const int lr = m * 4 + lr0;
            const float4 sv = *reinterpret_cast<const float4*>(&SP[lr * STRIDE + j * 4]);
            const float4 nv = *reinterpret_cast<const float4*>(&SN[lr * STRIDE + j * 4]);
            *reinterpret_cast<float4*>(so + (size_t)lr * LLEN + j * 4) = sv;
            *reinterpret_cast<float4*>(no + (size_t)lr * LLEN + j * 4) = nv;
        }
        __syncwarp();   // SP/SN reads done before next chunk's STS
    }
}

extern "C" void kernel_launch(void* const* d_in, const int* in_sizes, int n_in,
                              void* d_out, int out_size)
{
    const float* I = (const float*)d_in[0];
    const size_t total = (size_t)in_sizes[0];   // B * L
    const int B = (int)(total / LLEN);          // 16384

    float* outSpk = (float*)d_out;
    float* outNum = outSpk + total;

    lif_kernel<<<B / 32, 32>>>(I, outSpk, outNum);  // 512 single-warp CTAs
}